// round 7
// baseline (speedup 1.0000x reference)
#include <cuda_runtime.h>

#define NQ   12
#define DIM  4096
#define NL   5
#define NT   256
// pad-2 layout: loc(j) = j + 2*(j>>4) -> stride-18 rows, 16B-aligned rows
#define PAD_DIM (DIM + 2 * (DIM / 16))   // 4608 ull = 36 KB per element

typedef unsigned long long ull;

__device__ __forceinline__ ull f32x2_mul(ull a, ull b) {
    ull r;
    asm("mul.rn.f32x2 %0, %1, %2;" : "=l"(r) : "l"(a), "l"(b));
    return r;
}
__device__ __forceinline__ ull f32x2_fma(ull a, ull b, ull c) {
    ull r;
    asm("fma.rn.f32x2 %0, %1, %2, %3;" : "=l"(r) : "l"(a), "l"(b), "l"(c));
    return r;
}
__device__ __forceinline__ ull swap_halves(ull v) {
    uint2 t = *reinterpret_cast<uint2*>(&v);
    uint2 s = make_uint2(t.y, t.x);
    return *reinterpret_cast<ull*>(&s);
}
__device__ __forceinline__ ull pack2(float lo, float hi) {
    uint2 t = make_uint2(__float_as_uint(lo), __float_as_uint(hi));
    return *reinterpret_cast<ull*>(&t);
}
__device__ __forceinline__ float2 cmul(float2 a, float2 b) {
    return make_float2(a.x * b.x - a.y * b.y, a.x * b.y + a.y * b.x);
}

// apply 4 gates: register-nibble bit m (pair stride 1<<m) <-> qubit QBASE - m
// U layout per qubit q: 4 x ulonglong2 = {c00,d00},{c01,d01},{c10,d10},{c11,d11}
template <int QBASE>
__device__ __forceinline__ void gates4p(ull a[16], const ulonglong2* __restrict__ U) {
    #pragma unroll
    for (int m = 0; m < 4; m++) {
        const int q = QBASE - m;
        const ulonglong2 p0 = U[q * 4 + 0];
        const ulonglong2 p1 = U[q * 4 + 1];
        const ulonglong2 p2 = U[q * 4 + 2];
        const ulonglong2 p3 = U[q * 4 + 3];
        #pragma unroll
        for (int k = 0; k < 16; k++) {
            if (!(k & (1 << m))) {
                ull s0 = a[k], s1 = a[k | (1 << m)];
                ull s0w = swap_halves(s0), s1w = swap_halves(s1);
                ull n0 = f32x2_mul(p0.x, s0);
                n0 = f32x2_fma(p0.y, s0w, n0);
                n0 = f32x2_fma(p1.x, s1,  n0);
                n0 = f32x2_fma(p1.y, s1w, n0);
                ull n1 = f32x2_mul(p2.x, s0);
                n1 = f32x2_fma(p2.y, s0w, n1);
                n1 = f32x2_fma(p3.x, s1,  n1);
                n1 = f32x2_fma(p3.y, s1w, n1);
                a[k] = n0; a[k | (1 << m)] = n1;
            }
        }
    }
}

__global__ void __launch_bounds__(NT, 2)
qnet_kernel(const float* __restrict__ x,
            const float* __restrict__ iw,
            const float* __restrict__ th,
            const float* __restrict__ ow,
            float* __restrict__ out,
            int nb) {
    extern __shared__ __align__(16) ull dsm[];
    ull* st0 = dsm;                                    // elem-0 state (36 KB)
    ull* st1 = dsm + PAD_DIM;                          // elem-1 state (36 KB)
    ulonglong2* Up = reinterpret_cast<ulonglong2*>(dsm + 2 * PAD_DIM); // [2][NL*NQ*4]
    float2* U00s = reinterpret_cast<float2*>(Up + 2 * NL * NQ * 4);    // [2][NQ]
    float2* U10s = U00s + 2 * NQ;                                       // [2][NQ]
    float*  red  = reinterpret_cast<float*>(U10s + 2 * NQ);             // [2][2][8]

    const int tid = threadIdx.x;
    const int b0  = 2 * blockIdx.x;

    // ---- build ALL gates for BOTH elements: one thread per (elem,layer,qubit) ----
    if (tid < 2 * NL * NQ) {
        const int e  = (tid >= NL * NQ);
        const int li = tid - e * (NL * NQ);
        const int l  = li / NQ, q = li - l * NQ;
        const int be = b0 + e;
        float xv  = (be < nb) ? x[be * NQ + q] : 0.f;
        float xin = tanhf(xv);
        float g  = 0.5f * iw[l * NQ + q] * xin;
        float aa = 0.5f * th[(l * NQ + q) * 2 + 0];
        float bb = 0.5f * th[(l * NQ + q) * 2 + 1];
        float sg, cg, sa, ca, sb, cb;
        __sincosf(g,  &sg, &cg);
        __sincosf(aa, &sa, &ca);
        __sincosf(bb, &sb, &cb);
        float cc = ca * cg, ss = sa * sg, sc = sa * cg, cs = ca * sg;
        float2 e0 = make_float2(cb, -sb);
        float2 e1 = make_float2(cb,  sb);
        float2 u00 = cmul(e0, make_float2(cc,   ss));
        float2 u01 = cmul(e0, make_float2(-sc, -cs));
        float2 u10 = cmul(e1, make_float2(sc,  -cs));
        float2 u11 = cmul(e1, make_float2(cc,  -ss));
        ulonglong2* Uq = Up + ((e * NL + l) * NQ + q) * 4;
        Uq[0] = make_ulonglong2(pack2(u00.x, u00.x), pack2(-u00.y, u00.y));
        Uq[1] = make_ulonglong2(pack2(u01.x, u01.x), pack2(-u01.y, u01.y));
        Uq[2] = make_ulonglong2(pack2(u10.x, u10.x), pack2(-u10.y, u10.y));
        Uq[3] = make_ulonglong2(pack2(u11.x, u11.x), pack2(-u11.y, u11.y));
        if (l == 0) { U00s[e * NQ + q] = u00; U10s[e * NQ + q] = u10; }
    }

    // ---- CNOT-ring scatter map (inverse perm), GF(2)-linear closed form ----
    int gt = tid ^ (tid >> 1); gt ^= gt >> 2; gt ^= gt >> 4;
    const int par_t = gt & 1;
    const int F_t   = gt ^ (par_t << 11);
    const int DSTK[16] = {0x000, 0x9FF, 0xBFF, 0x200, 0xFFF, 0x600, 0x400, 0xDFF,
                          0x7FF, 0xE00, 0xC00, 0x5FF, 0x800, 0x1FF, 0x3FF, 0xA00};
    const bool S01K[16] = {0,1,1,0, 0,1,1,0, 1,0,0,1, 1,0,0,1};
    const bool S23K[16] = {0,1,0,1, 0,1,0,1, 0,1,0,1, 0,1,0,1};

    const int bB = 18 * (tid & 0xF0) + (tid & 15);   // phase B: k at bB + 18k
    const int bC = tid + 2 * (tid >> 4);             // phase C: k at bC + 288k
    ulonglong2* s0_128 = reinterpret_cast<ulonglong2*>(st0);
    ulonglong2* s1_128 = reinterpret_cast<ulonglong2*>(st1);

    ull a0[16], a1[16];
    __syncthreads();

    // ---------------- layer 0: product state, scatter-stored (post-perm) -------
    #pragma unroll
    for (int e = 0; e < 2; e++) {
        const float2* U00 = U00s + e * NQ;
        const float2* U10 = U10s + e * NQ;
        ull* ste = e ? st1 : st0;
        float2 plow = make_float2(1.f, 0.f);
        #pragma unroll
        for (int p = 0; p < 8; p++) {
            float2 row = ((tid >> p) & 1) ? U10[11 - p] : U00[11 - p];
            plow = cmul(plow, row);
        }
        #pragma unroll
        for (int k = 0; k < 16; k++) {
            float2 amp = plow;
            #pragma unroll
            for (int m = 0; m < 4; m++) {
                float2 row = ((k >> m) & 1) ? U10[3 - m] : U00[3 - m];
                amp = cmul(amp, row);
            }
            int d = DSTK[k] ^ F_t;
            ste[d + 2 * (d >> 4)] = pack2(amp.x, amp.y);
        }
    }
    __syncthreads();

    // ---------------- layers 1..4 ---------------------------------------------
    #pragma unroll 1
    for (int l = 1; l < NL; l++) {
        const ulonglong2* Ul0 = Up + (l * NQ) * 4;
        const ulonglong2* Ul1 = Up + ((NL + l) * NQ) * 4;

        // phase A: thread-local contiguous rows, 128-bit accesses
        #pragma unroll
        for (int q = 0; q < 8; q++) {
            ulonglong2 v = s0_128[9 * tid + q];
            a0[2 * q] = v.x; a0[2 * q + 1] = v.y;
        }
        #pragma unroll
        for (int q = 0; q < 8; q++) {
            ulonglong2 v = s1_128[9 * tid + q];
            a1[2 * q] = v.x; a1[2 * q + 1] = v.y;
        }
        gates4p<11>(a0, Ul0);
        #pragma unroll
        for (int q = 0; q < 8; q++)
            s0_128[9 * tid + q] = make_ulonglong2(a0[2 * q], a0[2 * q + 1]);
        gates4p<11>(a1, Ul1);
        #pragma unroll
        for (int q = 0; q < 8; q++)
            s1_128[9 * tid + q] = make_ulonglong2(a1[2 * q], a1[2 * q + 1]);
        __syncwarp();                             // A->B exchange is intra-half-warp

        // phase B
        #pragma unroll
        for (int k = 0; k < 16; k++) a0[k] = st0[bB + 18 * k];
        #pragma unroll
        for (int k = 0; k < 16; k++) a1[k] = st1[bB + 18 * k];
        gates4p<7>(a0, Ul0);
        #pragma unroll
        for (int k = 0; k < 16; k++) st0[bB + 18 * k] = a0[k];
        gates4p<7>(a1, Ul1);
        #pragma unroll
        for (int k = 0; k < 16; k++) st1[bB + 18 * k] = a1[k];
        __syncthreads();                          // B->C crosses warps

        // phase C (+ CNOT-ring scatter except last layer)
        #pragma unroll
        for (int k = 0; k < 16; k++) a0[k] = st0[bC + 288 * k];
        #pragma unroll
        for (int k = 0; k < 16; k++) a1[k] = st1[bC + 288 * k];
        gates4p<3>(a0, Ul0);
        gates4p<3>(a1, Ul1);
        if (l != NL - 1) {
            #pragma unroll
            for (int k = 0; k < 16; k++) {
                int d = DSTK[k] ^ F_t;
                int loc = d + 2 * (d >> 4);
                st0[loc] = a0[k];
                st1[loc] = a1[k];
            }
            __syncthreads();
        }
    }

    // ---------------- measurement fused into last phase-C registers ------------
    float e01v[2], e23v[2];
    #pragma unroll
    for (int e = 0; e < 2; e++) {
        ull* a = e ? a1 : a0;
        float P0 = 0.f, P1 = 0.f, Q0 = 0.f, Q1 = 0.f;
        #pragma unroll
        for (int k = 0; k < 16; k++) {
            float2 v = *reinterpret_cast<float2*>(&a[k]);
            float pr = v.x * v.x + v.y * v.y;
            if (S01K[k]) P1 += pr; else P0 += pr;
            if (S23K[k]) Q1 += pr; else Q0 += pr;
        }
        float e01 = P0 - P1;
        if (par_t) e01 = -e01;
        float e23 = Q0 - Q1;
        #pragma unroll
        for (int off = 16; off > 0; off >>= 1) {
            e01 += __shfl_down_sync(0xffffffffu, e01, off);
            e23 += __shfl_down_sync(0xffffffffu, e23, off);
        }
        e01v[e] = e01; e23v[e] = e23;
    }
    if ((tid & 31) == 0) {
        int w = tid >> 5;
        red[0 * 16 + 0 * 8 + w] = e01v[0];
        red[0 * 16 + 1 * 8 + w] = e23v[0];
        red[1 * 16 + 0 * 8 + w] = e01v[1];
        red[1 * 16 + 1 * 8 + w] = e23v[1];
    }
    __syncthreads();
    if (tid == 0) {
        float o0 = ow[0], o1 = ow[1];
        float s00 = 0.f, s01 = 0.f, s10 = 0.f, s11 = 0.f;
        #pragma unroll
        for (int w = 0; w < 8; w++) {
            s00 += red[0 * 16 + 0 * 8 + w];
            s01 += red[0 * 16 + 1 * 8 + w];
            s10 += red[1 * 16 + 0 * 8 + w];
            s11 += red[1 * 16 + 1 * 8 + w];
        }
        out[b0 * 2 + 0] = o0 * s00;
        out[b0 * 2 + 1] = o1 * s01;
        if (b0 + 1 < nb) {
            out[(b0 + 1) * 2 + 0] = o0 * s10;
            out[(b0 + 1) * 2 + 1] = o1 * s11;
        }
    }
}

extern "C" void kernel_launch(void* const* d_in, const int* in_sizes, int n_in,
                              void* d_out, int out_size) {
    const float* x  = (const float*)d_in[0];   // (BATCH, 12)
    const float* iw = (const float*)d_in[1];   // (5, 12)
    const float* th = (const float*)d_in[2];   // (5, 12, 2)
    const float* ow = (const float*)d_in[3];   // (2,)
    float* out = (float*)d_out;                // (BATCH, 2)
    int batch = in_sizes[0] / NQ;
    int grid  = (batch + 1) / 2;

    size_t shmem = (size_t)(2 * PAD_DIM) * 8            // two state buffers
                 + (size_t)(2 * NL * NQ * 4) * 16       // packed gate coeffs
                 + (size_t)(2 * NQ) * 8 * 2             // U00s + U10s
                 + 2 * 2 * 8 * 4;                       // reduction scratch
    cudaFuncSetAttribute(qnet_kernel,
                         cudaFuncAttributeMaxDynamicSharedMemorySize, (int)shmem);
    qnet_kernel<<<grid, NT, shmem>>>(x, iw, th, ow, out, batch);
}